// round 3
// baseline (speedup 1.0000x reference)
#include <cuda_runtime.h>

#define Bq 64
#define Nq 1024
#define Cq 256
#define TN 128
#define TK 128
#define NCTAS (Bq * (Nq / TN))   // 512

// Scratch (no allocations allowed): codeword norms, per-CTA loss partials, batch order.
__device__ float g_cnorm[3840];          // 256+512+1024+2048 rows
__device__ float g_losspart[NCTAS];
__device__ int   g_order[Bq];

// ---------------------------------------------------------------------------
// Kernel 1: ||c_k||^2 for all 4 codebooks. One warp per codeword row.
// ---------------------------------------------------------------------------
__global__ void cnorm_kernel(const float* __restrict__ cb0, const float* __restrict__ cb1,
                             const float* __restrict__ cb2, const float* __restrict__ cb3) {
    int gw   = (blockIdx.x * blockDim.x + threadIdx.x) >> 5;
    int lane = threadIdx.x & 31;
    if (gw >= 3840) return;
    const float* src; int row;
    if      (gw < 256)  { src = cb0; row = gw; }
    else if (gw < 768)  { src = cb1; row = gw - 256; }
    else if (gw < 1792) { src = cb2; row = gw - 768; }
    else                { src = cb3; row = gw - 1792; }
    const float4* p = reinterpret_cast<const float4*>(src + (size_t)row * Cq);
    float s = 0.f;
#pragma unroll
    for (int i = 0; i < 2; i++) {
        float4 v = p[lane + 32 * i];
        s += v.x * v.x + v.y * v.y + v.z * v.z + v.w * v.w;
    }
#pragma unroll
    for (int o = 16; o; o >>= 1) s += __shfl_xor_sync(0xffffffffu, s, o);
    if (lane == 0) g_cnorm[gw] = s;
}

// ---------------------------------------------------------------------------
// Kernel 2: build batch schedule, heaviest expert (largest K) first.
// ---------------------------------------------------------------------------
__global__ void schedule_kernel(const int* __restrict__ expert_idx) {
    if (blockIdx.x == 0 && threadIdx.x == 0) {
        int pos = 0;
        for (int e = 3; e >= 0; e--)
            for (int b = 0; b < Bq; b++)
                if (expert_idx[b] == e) g_order[pos++] = b;
    }
}

// ---------------------------------------------------------------------------
// Kernel 3: main VQ kernel. CTA = (token tile of 128) x (one batch).
// Register-tiled 128x128 distance GEMM in fp32, fused argmin + outputs + loss.
// Distances mimic the reference's fp32 rounding structure:
//   d = fl( fl(zn + cn) - 2*g )   (the x2 is exact; the FMA form is identical)
// so the comparison happens on the same ~ulp(256)=3e-5 grid as the reference.
// ---------------------------------------------------------------------------
__global__ __launch_bounds__(256, 2)
void vq_main_kernel(const float* __restrict__ z_e, const int* __restrict__ expert_idx,
                    const float* __restrict__ cb0, const float* __restrict__ cb1,
                    const float* __restrict__ cb2, const float* __restrict__ cb3,
                    float* __restrict__ out) {
    __shared__ float zT[16][TN];       // C-chunk x tokens (transposed)
    __shared__ float cT[16][TK];       // C-chunk x codes  (transposed)
    __shared__ float redv[TN][17];
    __shared__ int   redi[TN][17];
    __shared__ int   s_bidx[TN];
    __shared__ float s_warp[8];
    __shared__ float s_zn[TN];         // per-token ||z||^2

    const int tid = threadIdx.x;
    const int tx = tid & 15, ty = tid >> 4;
    const int b  = g_order[blockIdx.y];
    const int n0 = blockIdx.x * TN;
    const int e  = expert_idx[b];
    const int K  = 256 << e;
    const float* cb    = (e == 0) ? cb0 : (e == 1) ? cb1 : (e == 2) ? cb2 : cb3;
    const int    cnoff = (e == 0) ? 0 : (e == 1) ? 256 : (e == 2) ? 768 : 1792;
    const float* zptr  = z_e + ((size_t)b * Nq + n0) * Cq;

    // Per-token z-norms once up front.
    if (tid < TN) {
        const float4* zp = reinterpret_cast<const float4*>(zptr + (size_t)tid * Cq);
        float s = 0.f;
#pragma unroll 8
        for (int i = 0; i < 64; i++) {
            float4 v = zp[i];
            s += v.x * v.x + v.y * v.y + v.z * v.z + v.w * v.w;
        }
        s_zn[tid] = s;
    }
    __syncthreads();

    float zn_reg[8];
#pragma unroll
    for (int i = 0; i < 8; i++) zn_reg[i] = s_zn[ty * 8 + i];

    float bestv = 3.4e38f;
    int   besti = 0;

    for (int k0 = 0; k0 < K; k0 += TK) {
        float acc[8][8];
#pragma unroll
        for (int i = 0; i < 8; i++)
#pragma unroll
            for (int j = 0; j < 8; j++) acc[i][j] = 0.f;

        const float* cbk = cb + (size_t)k0 * Cq;

        for (int cc0 = 0; cc0 < Cq; cc0 += 16) {
            __syncthreads();
            // Load + transpose 128x16 tiles of z and cb into smem.
#pragma unroll
            for (int l = 0; l < 2; l++) {
                int idx = tid + l * 256;         // 0..511 over 512 float4s
                int row = idx >> 2;
                int c4  = (idx & 3) << 2;
                float4 v = *reinterpret_cast<const float4*>(zptr + row * Cq + cc0 + c4);
                zT[c4 + 0][row] = v.x; zT[c4 + 1][row] = v.y;
                zT[c4 + 2][row] = v.z; zT[c4 + 3][row] = v.w;
                float4 w = *reinterpret_cast<const float4*>(cbk + row * Cq + cc0 + c4);
                cT[c4 + 0][row] = w.x; cT[c4 + 1][row] = w.y;
                cT[c4 + 2][row] = w.z; cT[c4 + 3][row] = w.w;
            }
            __syncthreads();
#pragma unroll
            for (int cc = 0; cc < 16; cc++) {
                float a[8], bb[8];
                *reinterpret_cast<float4*>(&a[0])  = *reinterpret_cast<const float4*>(&zT[cc][ty * 8]);
                *reinterpret_cast<float4*>(&a[4])  = *reinterpret_cast<const float4*>(&zT[cc][ty * 8 + 4]);
                *reinterpret_cast<float4*>(&bb[0]) = *reinterpret_cast<const float4*>(&cT[cc][tx * 8]);
                *reinterpret_cast<float4*>(&bb[4]) = *reinterpret_cast<const float4*>(&cT[cc][tx * 8 + 4]);
#pragma unroll
                for (int i = 0; i < 8; i++)
#pragma unroll
                    for (int j = 0; j < 8; j++)
                        acc[i][j] += a[i] * bb[j];
            }
        }

        // dist = fl(fl(zn + cn) - 2*g), matching the reference's fp32 rounding.
        float cn[8];
#pragma unroll
        for (int j = 0; j < 8; j++) cn[j] = g_cnorm[cnoff + k0 + tx * 8 + j];
#pragma unroll
        for (int i = 0; i < 8; i++) {
            float mv = 3.4e38f; int mj = 0;
#pragma unroll
            for (int j = 0; j < 8; j++) {
                float t1 = __fadd_rn(zn_reg[i], cn[j]);
                float d  = __fadd_rn(t1, -2.0f * acc[i][j]);  // 2*acc exact
                if (d < mv) { mv = d; mj = j; }   // strict < : first-min on ties
            }
            redv[ty * 8 + i][tx] = mv;
            redi[ty * 8 + i][tx] = k0 + tx * 8 + mj;
        }
        __syncthreads();
        if (tid < TN) {
#pragma unroll
            for (int ee = 0; ee < 16; ee++) {     // ascending tx = ascending code index
                float v = redv[tid][ee];
                if (v < bestv) { bestv = v; besti = redi[tid][ee]; }
            }
        }
        // next k-tile's smem writes are behind the C-loop __syncthreads()
    }

    // loss per token = ||z - c||^2 = bestv (full distance already)
    float lossv = 0.f;
    if (tid < TN) {
        lossv = bestv;
        s_bidx[tid] = besti;
        out[(size_t)Bq * Nq * Cq + (size_t)b * Nq + n0 + tid] = (float)besti;
    }
#pragma unroll
    for (int o = 16; o; o >>= 1) lossv += __shfl_xor_sync(0xffffffffu, lossv, o);
    if ((tid & 31) == 0) s_warp[tid >> 5] = lossv;
    __syncthreads();
    if (tid == 0)
        g_losspart[blockIdx.y * (Nq / TN) + blockIdx.x] =
            s_warp[0] + s_warp[1] + s_warp[2] + s_warp[3];

    // write z_q rows: warp-per-token, fully coalesced
    const int warpid = tid >> 5, lane = tid & 31;
    float* zq = out + ((size_t)b * Nq + n0) * Cq;
    for (int t = warpid; t < TN; t += 8) {
        const float4* srcp = reinterpret_cast<const float4*>(cb + (size_t)s_bidx[t] * Cq);
        float4* dstp = reinterpret_cast<float4*>(zq + (size_t)t * Cq);
        dstp[lane]      = srcp[lane];
        dstp[lane + 32] = srcp[lane + 32];
    }
}

// ---------------------------------------------------------------------------
// Kernel 4: deterministic final loss reduction.
// ---------------------------------------------------------------------------
__global__ void loss_kernel(float* __restrict__ out) {
    __shared__ float sw[16];
    int tid = threadIdx.x;                 // 512 threads = NCTAS
    float v = g_losspart[tid];
#pragma unroll
    for (int o = 16; o; o >>= 1) v += __shfl_xor_sync(0xffffffffu, v, o);
    if ((tid & 31) == 0) sw[tid >> 5] = v;
    __syncthreads();
    if (tid == 0) {
        float s = 0.f;
        for (int i = 0; i < 16; i++) s += sw[i];
        // vq_loss = 1.25 * S / (B*N*C*C); B*N*C*C = 2^32 exactly
        out[(size_t)Bq * Nq * Cq + (size_t)Bq * Nq] = 1.25f * s / 4294967296.0f;
    }
}

extern "C" void kernel_launch(void* const* d_in, const int* in_sizes, int n_in,
                              void* d_out, int out_size) {
    const float* z_e  = (const float*)d_in[0];
    const int*   eidx = (const int*)d_in[1];
    const float* cb0  = (const float*)d_in[2];
    const float* cb1  = (const float*)d_in[3];
    const float* cb2  = (const float*)d_in[4];
    const float* cb3  = (const float*)d_in[5];
    float* out = (float*)d_out;

    cnorm_kernel<<<480, 256>>>(cb0, cb1, cb2, cb3);
    schedule_kernel<<<1, 32>>>(eidx);
    dim3 grid(Nq / TN, Bq);
    vq_main_kernel<<<grid, 256>>>(z_e, eidx, cb0, cb1, cb2, cb3, out);
    loss_kernel<<<1, 512>>>(out);
}

// round 4
// speedup vs baseline: 1.4696x; 1.4696x over previous
#include <cuda_runtime.h>
#include <cuda_bf16.h>
#include <stdint.h>

#define Bq 64
#define Nq 1024
#define Cq 256
#define TN 128
#define TK 128
#define MARGIN 0.15f
#define NZ4 (Bq * Nq * Cq / 4)     // 4194304 float4 of z
#define NC4 (3840 * Cq / 4)        // 245760 float4 of codebooks

// Scratch (no allocations allowed)
__device__ float g_cnorm[3840];
__device__ float g_losspart[512];
__device__ int   g_order[Bq];
__device__ __nv_bfloat16 g_zbf[(size_t)Bq * Nq * Cq];   // 33.5 MB
__device__ __nv_bfloat16 g_cbf[3840 * Cq];              // 2 MB

// SMEM layout (dynamic)
#define SM_Z    0
#define SM_C    65536
#define SM_CN   131072
#define SM_ZN   131584
#define SM_MIN  132096
#define SM_KEY  132608
#define SM_BIDX 133632
#define SM_WARP 134144
#define SM_TOTAL 134208

// ---------------------------------------------------------------------------
// bf16 conversion of z and all codebooks (one-time per launch)
// ---------------------------------------------------------------------------
__global__ void cvt_kernel(const float* __restrict__ z,
                           const float* __restrict__ c0, const float* __restrict__ c1,
                           const float* __restrict__ c2, const float* __restrict__ c3) {
    int i = blockIdx.x * blockDim.x + threadIdx.x;
    float4 v;
    __nv_bfloat16* dst;
    if (i < NZ4) {
        v = reinterpret_cast<const float4*>(z)[i];
        dst = g_zbf + (size_t)i * 4;
    } else {
        int j = i - NZ4;
        if (j >= NC4) return;
        int fe = j * 4;
        const float* cp; int rel;
        if      (fe < 65536)  { cp = c0; rel = fe; }
        else if (fe < 196608) { cp = c1; rel = fe - 65536; }
        else if (fe < 458752) { cp = c2; rel = fe - 196608; }
        else                  { cp = c3; rel = fe - 458752; }
        v = *reinterpret_cast<const float4*>(cp + rel);
        dst = g_cbf + fe;
    }
    __nv_bfloat162 lo = __floats2bfloat162_rn(v.x, v.y);
    __nv_bfloat162 hi = __floats2bfloat162_rn(v.z, v.w);
    uint2 u;
    u.x = *reinterpret_cast<uint32_t*>(&lo);
    u.y = *reinterpret_cast<uint32_t*>(&hi);
    *reinterpret_cast<uint2*>(dst) = u;
}

// ---------------------------------------------------------------------------
// ||c_k||^2 for all codebooks (fp32, reference-exact structure)
// ---------------------------------------------------------------------------
__global__ void cnorm_kernel(const float* __restrict__ cb0, const float* __restrict__ cb1,
                             const float* __restrict__ cb2, const float* __restrict__ cb3) {
    int gw   = (blockIdx.x * blockDim.x + threadIdx.x) >> 5;
    int lane = threadIdx.x & 31;
    if (gw >= 3840) return;
    const float* src; int row;
    if      (gw < 256)  { src = cb0; row = gw; }
    else if (gw < 768)  { src = cb1; row = gw - 256; }
    else if (gw < 1792) { src = cb2; row = gw - 768; }
    else                { src = cb3; row = gw - 1792; }
    const float4* p = reinterpret_cast<const float4*>(src + (size_t)row * Cq);
    float s = 0.f;
#pragma unroll
    for (int i = 0; i < 2; i++) {
        float4 v = p[lane + 32 * i];
        s += v.x * v.x + v.y * v.y + v.z * v.z + v.w * v.w;
    }
#pragma unroll
    for (int o = 16; o; o >>= 1) s += __shfl_xor_sync(0xffffffffu, s, o);
    if (lane == 0) g_cnorm[gw] = s;
}

// ---------------------------------------------------------------------------
// batch schedule: heaviest expert first (cuts wave-tail imbalance)
// ---------------------------------------------------------------------------
__global__ void schedule_kernel(const int* __restrict__ expert_idx) {
    if (blockIdx.x == 0 && threadIdx.x == 0) {
        int pos = 0;
        for (int e = 3; e >= 0; e--)
            for (int b = 0; b < Bq; b++)
                if (expert_idx[b] == e) g_order[pos++] = b;
    }
}

// ---------------------------------------------------------------------------
// helpers
// ---------------------------------------------------------------------------
__device__ __forceinline__ uint32_t sm_u32(const void* p) {
    return (uint32_t)__cvta_generic_to_shared(p);
}
// swizzled address: row stride 512B (256 bf16), 16B chunk XOR (row&7)
__device__ __forceinline__ uint32_t sw_addr(uint32_t base, int row, int kelem) {
    return base + (row << 9) + ((((kelem >> 3) ^ (row & 7))) << 4);
}

// Exact fp32 rescore of one (token, code) pair; reference rounding grid.
__device__ __noinline__ void rescore(const float4* __restrict__ z4,
                                     const float4* __restrict__ c4,
                                     float zn, float cn, int code,
                                     unsigned long long* keyp) {
    float sx = 0.f, sy = 0.f, sz = 0.f, sw = 0.f;
#pragma unroll 8
    for (int i = 0; i < 64; i++) {
        float4 a = z4[i]; float4 b = c4[i];
        sx = fmaf(a.x, b.x, sx); sy = fmaf(a.y, b.y, sy);
        sz = fmaf(a.z, b.z, sz); sw = fmaf(a.w, b.w, sw);
    }
    float dot = (sx + sy) + (sz + sw);
    float d = __fadd_rn(__fadd_rn(zn, cn), -2.0f * dot);
    unsigned long long key = ((unsigned long long)__float_as_uint(d) << 32) | (unsigned int)code;
    atomicMin(keyp, key);
}

// One 128(tokens) x 128(codes) x 256(C) bf16 MMA tile into acc[16][4].
__device__ __forceinline__ void mma_tile(uint32_t zbase, uint32_t cbase,
                                         int m_base, int lane, float (&acc)[16][4]) {
#pragma unroll
    for (int f = 0; f < 16; f++)
#pragma unroll
        for (int q = 0; q < 4; q++) acc[f][q] = 0.f;

    const int alr = m_base + (lane & 15);
    const int alk = (lane >> 4) << 3;
    const int br  = lane & 7;
    const int bn  = (lane & 16) ? 8 : 0;
    const int bk  = (lane & 8) ? 8 : 0;

#pragma unroll 2
    for (int kk = 0; kk < 16; kk++) {
        const int kb = kk << 4;
        uint32_t a0, a1, a2, a3;
        asm volatile("ldmatrix.sync.aligned.m8n8.x4.shared.b16 {%0,%1,%2,%3}, [%4];"
                     : "=r"(a0), "=r"(a1), "=r"(a2), "=r"(a3)
                     : "r"(sw_addr(zbase, alr, kb + alk)));
#pragma unroll
        for (int jp = 0; jp < 8; jp++) {
            const int nrow = jp * 16 + bn + br;
            uint32_t b0, b1, b2, b3;
            asm volatile("ldmatrix.sync.aligned.m8n8.x4.shared.b16 {%0,%1,%2,%3}, [%4];"
                         : "=r"(b0), "=r"(b1), "=r"(b2), "=r"(b3)
                         : "r"(sw_addr(cbase, nrow, kb + bk)));
            asm volatile("mma.sync.aligned.m16n8k16.row.col.f32.bf16.bf16.f32 "
                         "{%0,%1,%2,%3}, {%4,%5,%6,%7}, {%8,%9}, {%0,%1,%2,%3};"
                         : "+f"(acc[jp*2][0]), "+f"(acc[jp*2][1]),
                           "+f"(acc[jp*2][2]), "+f"(acc[jp*2][3])
                         : "r"(a0), "r"(a1), "r"(a2), "r"(a3), "r"(b0), "r"(b1));
            asm volatile("mma.sync.aligned.m16n8k16.row.col.f32.bf16.bf16.f32 "
                         "{%0,%1,%2,%3}, {%4,%5,%6,%7}, {%8,%9}, {%0,%1,%2,%3};"
                         : "+f"(acc[jp*2+1][0]), "+f"(acc[jp*2+1][1]),
                           "+f"(acc[jp*2+1][2]), "+f"(acc[jp*2+1][3])
                         : "r"(a0), "r"(a1), "r"(a2), "r"(a3), "r"(b2), "r"(b3));
        }
    }
}

// ---------------------------------------------------------------------------
// Main VQ kernel: bf16 tensor-core prefilter (pass 1) + exact rescore (pass 2)
// ---------------------------------------------------------------------------
__global__ __launch_bounds__(256, 1)
void vq_main_kernel(const float* __restrict__ z_e, const int* __restrict__ expert_idx,
                    const float* __restrict__ cb0, const float* __restrict__ cb1,
                    const float* __restrict__ cb2, const float* __restrict__ cb3,
                    float* __restrict__ out) {
    extern __shared__ char smem[];
    float* s_cn  = reinterpret_cast<float*>(smem + SM_CN);
    float* s_zn  = reinterpret_cast<float*>(smem + SM_ZN);
    float* s_min = reinterpret_cast<float*>(smem + SM_MIN);
    unsigned long long* s_key = reinterpret_cast<unsigned long long*>(smem + SM_KEY);
    int*   s_bidx = reinterpret_cast<int*>(smem + SM_BIDX);
    float* s_warp = reinterpret_cast<float*>(smem + SM_WARP);
    const uint32_t zbase = sm_u32(smem + SM_Z);
    const uint32_t cbase = sm_u32(smem + SM_C);

    const int tid = threadIdx.x;
    const int wid = tid >> 5, lane = tid & 31;
    const int m_base = wid * 16;
    const int b  = g_order[blockIdx.y];
    const int n0 = blockIdx.x * TN;
    const int e  = expert_idx[b];
    const int K  = 256 << e;
    const float* cb    = (e == 0) ? cb0 : (e == 1) ? cb1 : (e == 2) ? cb2 : cb3;
    const int    cnoff = (e == 0) ? 0 : (e == 1) ? 256 : (e == 2) ? 768 : 1792;
    const float* zptr = z_e + ((size_t)b * Nq + n0) * Cq;
    const __nv_bfloat16* zbfp = g_zbf + ((size_t)b * Nq + n0) * Cq;
    const __nv_bfloat16* cbfp = g_cbf + (size_t)cnoff * Cq;

    // per-token ||z||^2 (fp32, reference-structured)
    if (tid < TN) {
        const float4* zp = reinterpret_cast<const float4*>(zptr + (size_t)tid * Cq);
        float s = 0.f;
#pragma unroll 8
        for (int i = 0; i < 64; i++) {
            float4 v = zp[i];
            s += v.x * v.x + v.y * v.y + v.z * v.z + v.w * v.w;
        }
        s_zn[tid] = s;
    }

    // load z tile -> swizzled bf16 smem (16B chunks)
#pragma unroll
    for (int i = 0; i < 16; i++) {
        int idx = tid + i * 256;         // 4096 chunks
        int row = idx >> 5, ch = idx & 31;
        uint4 v = *reinterpret_cast<const uint4*>(
            reinterpret_cast<const char*>(zbfp) + row * 512 + ch * 16);
        *reinterpret_cast<uint4*>(smem + SM_Z + row * 512 + ((ch ^ (row & 7)) * 16)) = v;
    }
    __syncthreads();

    const int g  = lane >> 2, t2 = (lane & 3) << 1;
    const int tok_lo = m_base + g, tok_hi = tok_lo + 8;
    const float znlo = s_zn[tok_lo], znhi = s_zn[tok_hi];
    const float4* zrow_lo = reinterpret_cast<const float4*>(zptr + (size_t)tok_lo * Cq);
    const float4* zrow_hi = reinterpret_cast<const float4*>(zptr + (size_t)tok_hi * Cq);

    float acc[16][4];
    float mlo = 3.4e38f, mhi = 3.4e38f;

    // ---------------- PASS 1: bf16 min ----------------
    for (int k0 = 0; k0 < K; k0 += TK) {
        __syncthreads();
        const char* csrc = reinterpret_cast<const char*>(cbfp) + (size_t)k0 * 512;
#pragma unroll
        for (int i = 0; i < 16; i++) {
            int idx = tid + i * 256;
            int row = idx >> 5, ch = idx & 31;
            uint4 v = *reinterpret_cast<const uint4*>(csrc + row * 512 + ch * 16);
            *reinterpret_cast<uint4*>(smem + SM_C + row * 512 + ((ch ^ (row & 7)) * 16)) = v;
        }
        if (tid < TK) s_cn[tid] = g_cnorm[cnoff + k0 + tid];
        __syncthreads();

        mma_tile(zbase, cbase, m_base, lane, acc);

#pragma unroll
        for (int f = 0; f < 16; f++) {
            float cn0 = s_cn[f * 8 + t2], cn1 = s_cn[f * 8 + t2 + 1];
            float d00 = __fadd_rn(__fadd_rn(znlo, cn0), -2.f * acc[f][0]);
            float d01 = __fadd_rn(__fadd_rn(znlo, cn1), -2.f * acc[f][1]);
            float d10 = __fadd_rn(__fadd_rn(znhi, cn0), -2.f * acc[f][2]);
            float d11 = __fadd_rn(__fadd_rn(znhi, cn1), -2.f * acc[f][3]);
            mlo = fminf(mlo, fminf(d00, d01));
            mhi = fminf(mhi, fminf(d10, d11));
        }
    }
    // quad-reduce mins (lanes 4g..4g+3 share rows)
    mlo = fminf(mlo, __shfl_xor_sync(0xffffffffu, mlo, 1));
    mlo = fminf(mlo, __shfl_xor_sync(0xffffffffu, mlo, 2));
    mhi = fminf(mhi, __shfl_xor_sync(0xffffffffu, mhi, 1));
    mhi = fminf(mhi, __shfl_xor_sync(0xffffffffu, mhi, 2));
    if ((lane & 3) == 0) { s_min[tok_lo] = mlo; s_min[tok_hi] = mhi; }
    if (tid < TN) s_key[tid] = 0xFFFFFFFFFFFFFFFFull;
    __syncthreads();

    const float thrlo = s_min[tok_lo] + MARGIN;
    const float thrhi = s_min[tok_hi] + MARGIN;

    // ---------------- PASS 2: candidate collect + exact rescore ----------------
    for (int k0 = 0; k0 < K; k0 += TK) {
        __syncthreads();
        const char* csrc = reinterpret_cast<const char*>(cbfp) + (size_t)k0 * 512;
#pragma unroll
        for (int i = 0; i < 16; i++) {
            int idx = tid + i * 256;
            int row = idx >> 5, ch = idx & 31;
            uint4 v = *reinterpret_cast<const uint4*>(csrc + row * 512 + ch * 16);
            *reinterpret_cast<uint4*>(smem + SM_C + row * 512 + ((ch ^ (row & 7)) * 16)) = v;
        }
        if (tid < TK) s_cn[tid] = g_cnorm[cnoff + k0 + tid];
        __syncthreads();

        mma_tile(zbase, cbase, m_base, lane, acc);

#pragma unroll
        for (int f = 0; f < 16; f++) {
            float cn0 = s_cn[f * 8 + t2], cn1 = s_cn[f * 8 + t2 + 1];
            int c0i = k0 + f * 8 + t2, c1i = c0i + 1;
            float d00 = __fadd_rn(__fadd_rn(znlo, cn0), -2.f * acc[f][0]);
            float d01 = __fadd_rn(__fadd_rn(znlo, cn1), -2.f * acc[f][1]);
            float d10 = __fadd_rn(__fadd_rn(znhi, cn0), -2.f * acc[f][2]);
            float d11 = __fadd_rn(__fadd_rn(znhi, cn1), -2.f * acc[f][3]);
            if (d00 < thrlo) rescore(zrow_lo, reinterpret_cast<const float4*>(cb + (size_t)c0i * Cq), znlo, cn0, c0i, &s_key[tok_lo]);
            if (d01 < thrlo) rescore(zrow_lo, reinterpret_cast<const float4*>(cb + (size_t)c1i * Cq), znlo, cn1, c1i, &s_key[tok_lo]);
            if (d10 < thrhi) rescore(zrow_hi, reinterpret_cast<const float4*>(cb + (size_t)c0i * Cq), znhi, cn0, c0i, &s_key[tok_hi]);
            if (d11 < thrhi) rescore(zrow_hi, reinterpret_cast<const float4*>(cb + (size_t)c1i * Cq), znhi, cn1, c1i, &s_key[tok_hi]);
        }
    }
    __syncthreads();

    // ---------------- outputs ----------------
    float lossv = 0.f;
    if (tid < TN) {
        unsigned long long key = s_key[tid];
        int besti   = (int)(key & 0xFFFFFFFFull);
        float bestv = __uint_as_float((unsigned int)(key >> 32));
        lossv = bestv;
        s_bidx[tid] = besti;
        out[(size_t)Bq * Nq * Cq + (size_t)b * Nq + n0 + tid] = (float)besti;
    }
#pragma unroll
    for (int o = 16; o; o >>= 1) lossv += __shfl_xor_sync(0xffffffffu, lossv, o);
    if ((tid & 31) == 0) s_warp[tid >> 5] = lossv;
    __syncthreads();
    if (tid == 0)
        g_losspart[blockIdx.y * (Nq / TN) + blockIdx.x] =
            s_warp[0] + s_warp[1] + s_warp[2] + s_warp[3];

    // z_q rows: warp-per-token, coalesced fp32 copy
    float* zq = out + ((size_t)b * Nq + n0) * Cq;
    for (int t = wid; t < TN; t += 8) {
        const float4* srcp = reinterpret_cast<const float4*>(cb + (size_t)s_bidx[t] * Cq);
        float4* dstp = reinterpret_cast<float4*>(zq + (size_t)t * Cq);
        dstp[lane]      = srcp[lane];
        dstp[lane + 32] = srcp[lane + 32];
    }
}

// ---------------------------------------------------------------------------
// deterministic final loss reduction
// ---------------------------------------------------------------------------
__global__ void loss_kernel(float* __restrict__ out) {
    __shared__ float sw[16];
    int tid = threadIdx.x;                 // 512 threads
    float v = g_losspart[tid];
#pragma unroll
    for (int o = 16; o; o >>= 1) v += __shfl_xor_sync(0xffffffffu, v, o);
    if ((tid & 31) == 0) sw[tid >> 5] = v;
    __syncthreads();
    if (tid == 0) {
        float s = 0.f;
        for (int i = 0; i < 16; i++) s += sw[i];
        out[(size_t)Bq * Nq * Cq + (size_t)Bq * Nq] = 1.25f * s / 4294967296.0f;
    }
}

extern "C" void kernel_launch(void* const* d_in, const int* in_sizes, int n_in,
                              void* d_out, int out_size) {
    const float* z_e  = (const float*)d_in[0];
    const int*   eidx = (const int*)d_in[1];
    const float* cb0  = (const float*)d_in[2];
    const float* cb1  = (const float*)d_in[3];
    const float* cb2  = (const float*)d_in[4];
    const float* cb3  = (const float*)d_in[5];
    float* out = (float*)d_out;

    cudaFuncSetAttribute(vq_main_kernel, cudaFuncAttributeMaxDynamicSharedMemorySize, SM_TOTAL);

    cvt_kernel<<<(NZ4 + NC4 + 255) / 256, 256>>>(z_e, cb0, cb1, cb2, cb3);
    cnorm_kernel<<<480, 256>>>(cb0, cb1, cb2, cb3);
    schedule_kernel<<<1, 32>>>(eidx);
    dim3 grid(Nq / TN, Bq);
    vq_main_kernel<<<grid, 256, SM_TOTAL>>>(z_e, eidx, cb0, cb1, cb2, cb3, out);
    loss_kernel<<<1, 512>>>(out);
}

// round 5
// speedup vs baseline: 3.3015x; 2.2466x over previous
#include <cuda_runtime.h>
#include <cuda_bf16.h>
#include <stdint.h>

#define Bq 64
#define Nq 1024
#define Cq 256
#define TN 128
#define TK 128
#define MARGIN 0.15f
#define POOL 5120

// smem layout (bytes)
#define SM_Z    0          // 128 x 256 bf16 (swizzled)           65536
#define SM_C0   65536      // C tile buf0                         65536
#define SM_C1   131072     // C tile buf1                         65536
#define SM_CN   196608     // up to 2048 fp32 code norms           8192
#define SM_THR  204800     // 128 fp32 running thresholds           512
#define SM_ZN   205312     // 128 fp32 ||z||^2                      512
#define SM_TMIN 205824     // 2 x 128 fp32 per-half tile mins      1024
#define SM_KEY  206848     // 128 u64 result keys                  1024
#define SM_BIDX 207872     // 128 int                               512
#define SM_WARP 208384     // 8 fp32 + pad                           64
#define SM_CNT  208448     // pool counter + pad                     16
#define SM_POOL 208464     // POOL x u32                          20480
#define SM_TOTAL (SM_POOL + POOL * 4)   // 228944 <= 232448

// device scratch (no allocations allowed)
__device__ float g_cnorm[3840];
__device__ float g_losspart[512];
__device__ int   g_order[Bq];
__device__ __nv_bfloat16 g_cbf[3840 * Cq];   // bf16 codebooks, 2 MB

// ---------------------------------------------------------------------------
// Kernel 1: per-codeword ||c||^2 (fp32) + bf16 conversion of all codebooks.
// One warp per codeword row.
// ---------------------------------------------------------------------------
__global__ void cnorm_cvt_kernel(const float* __restrict__ cb0, const float* __restrict__ cb1,
                                 const float* __restrict__ cb2, const float* __restrict__ cb3) {
    int gw   = (blockIdx.x * blockDim.x + threadIdx.x) >> 5;
    int lane = threadIdx.x & 31;
    if (gw >= 3840) return;
    const float* src; int row;
    if      (gw < 256)  { src = cb0; row = gw; }
    else if (gw < 768)  { src = cb1; row = gw - 256; }
    else if (gw < 1792) { src = cb2; row = gw - 768; }
    else                { src = cb3; row = gw - 1792; }
    const float4* p = reinterpret_cast<const float4*>(src + (size_t)row * Cq);
    float4 v0 = p[lane], v1 = p[lane + 32];
    float s = v0.x*v0.x + v0.y*v0.y + v0.z*v0.z + v0.w*v0.w
            + v1.x*v1.x + v1.y*v1.y + v1.z*v1.z + v1.w*v1.w;
#pragma unroll
    for (int o = 16; o; o >>= 1) s += __shfl_xor_sync(0xffffffffu, s, o);
    if (lane == 0) g_cnorm[gw] = s;
    // bf16 conversion
    uint2* dst = reinterpret_cast<uint2*>(g_cbf + (size_t)gw * Cq);
    __nv_bfloat162 a0 = __floats2bfloat162_rn(v0.x, v0.y);
    __nv_bfloat162 a1 = __floats2bfloat162_rn(v0.z, v0.w);
    __nv_bfloat162 b0 = __floats2bfloat162_rn(v1.x, v1.y);
    __nv_bfloat162 b1 = __floats2bfloat162_rn(v1.z, v1.w);
    uint2 ua, ub;
    ua.x = *reinterpret_cast<uint32_t*>(&a0); ua.y = *reinterpret_cast<uint32_t*>(&a1);
    ub.x = *reinterpret_cast<uint32_t*>(&b0); ub.y = *reinterpret_cast<uint32_t*>(&b1);
    dst[lane] = ua; dst[lane + 32] = ub;
}

// ---------------------------------------------------------------------------
// Kernel 2: batch schedule, heaviest expert first.
// ---------------------------------------------------------------------------
__global__ void schedule_kernel(const int* __restrict__ expert_idx) {
    if (blockIdx.x == 0 && threadIdx.x == 0) {
        int pos = 0;
        for (int e = 3; e >= 0; e--)
            for (int b = 0; b < Bq; b++)
                if (expert_idx[b] == e) g_order[pos++] = b;
    }
}

// ---------------------------------------------------------------------------
// helpers
// ---------------------------------------------------------------------------
__device__ __forceinline__ uint32_t sm_u32(const void* p) {
    return (uint32_t)__cvta_generic_to_shared(p);
}
// swizzled smem address: row stride 512B (256 bf16), 16B chunk XOR (row&7)
__device__ __forceinline__ uint32_t sw_addr(uint32_t base, int row, int kelem) {
    return base + (row << 9) + ((((kelem >> 3) ^ (row & 7))) << 4);
}

__device__ __forceinline__ void prefetch_c(const __nv_bfloat16* cbfp, int k0,
                                           char* sbuf, int tid) {
    const char* src = reinterpret_cast<const char*>(cbfp) + (size_t)k0 * 512;
#pragma unroll
    for (int i = 0; i < 16; i++) {
        int idx = tid + i * 256;
        int row = idx >> 5, ch = idx & 31;
        uint32_t dst = sm_u32(sbuf + row * 512 + ((ch ^ (row & 7)) * 16));
        asm volatile("cp.async.cg.shared.global [%0], [%1], 16;"
                     :: "r"(dst), "l"(src + row * 512 + ch * 16));
    }
}

// ---------------------------------------------------------------------------
// Main kernel: single bf16 MMA pass with running-threshold candidate
// collection (+1 tile-0 recollect), then exact fp32 rescore of candidates.
// ---------------------------------------------------------------------------
__global__ __launch_bounds__(256, 1)
void vq_main_kernel(const float* __restrict__ z_e, const int* __restrict__ expert_idx,
                    const float* __restrict__ cb0, const float* __restrict__ cb1,
                    const float* __restrict__ cb2, const float* __restrict__ cb3,
                    float* __restrict__ out) {
    extern __shared__ char smem[];
    float* s_cnall = reinterpret_cast<float*>(smem + SM_CN);
    float* s_thr   = reinterpret_cast<float*>(smem + SM_THR);
    float* s_zn    = reinterpret_cast<float*>(smem + SM_ZN);
    float* s_tmin  = reinterpret_cast<float*>(smem + SM_TMIN);
    unsigned long long* s_key = reinterpret_cast<unsigned long long*>(smem + SM_KEY);
    int*      s_bidx = reinterpret_cast<int*>(smem + SM_BIDX);
    float*    s_warp = reinterpret_cast<float*>(smem + SM_WARP);
    unsigned* s_cnt  = reinterpret_cast<unsigned*>(smem + SM_CNT);
    unsigned* s_pool = reinterpret_cast<unsigned*>(smem + SM_POOL);
    const uint32_t zbase = sm_u32(smem + SM_Z);

    const int tid = threadIdx.x;
    const int wid = tid >> 5, lane = tid & 31;
    const int mrow  = (wid & 3) * 32;      // 4-way M split
    const int ncol0 = (wid >> 2) * 64;     // 2-way N split
    const int b  = g_order[blockIdx.y];
    const int n0 = blockIdx.x * TN;
    const int e  = expert_idx[b];
    const int K  = 256 << e;
    const float* cb    = (e == 0) ? cb0 : (e == 1) ? cb1 : (e == 2) ? cb2 : cb3;
    const int    cnoff = (e == 0) ? 0 : (e == 1) ? 256 : (e == 2) ? 768 : 1792;
    const float* zptr = z_e + ((size_t)b * Nq + n0) * Cq;
    const __nv_bfloat16* cbfp = g_cbf + (size_t)cnoff * Cq;

    // init
    if (tid < 128) { s_thr[tid] = 3.4e38f; s_key[tid] = 0xFFFFFFFFFFFFFFFFull; }
    if (tid == 0) *s_cnt = 0;
    for (int i = tid; i < K; i += 256) s_cnall[i] = g_cnorm[cnoff + i];

    // convert this CTA's 128 z rows fp32 -> bf16 swizzled smem
#pragma unroll
    for (int i = 0; i < 16; i++) {
        int idx = tid + i * 256;
        int row = idx >> 5, ch = idx & 31;
        const float* sp = zptr + row * Cq + ch * 8;
        float4 f0 = *reinterpret_cast<const float4*>(sp);
        float4 f1 = *reinterpret_cast<const float4*>(sp + 4);
        __nv_bfloat162 p0 = __floats2bfloat162_rn(f0.x, f0.y);
        __nv_bfloat162 p1 = __floats2bfloat162_rn(f0.z, f0.w);
        __nv_bfloat162 p2 = __floats2bfloat162_rn(f1.x, f1.y);
        __nv_bfloat162 p3 = __floats2bfloat162_rn(f1.z, f1.w);
        uint4 u;
        u.x = *reinterpret_cast<uint32_t*>(&p0); u.y = *reinterpret_cast<uint32_t*>(&p1);
        u.z = *reinterpret_cast<uint32_t*>(&p2); u.w = *reinterpret_cast<uint32_t*>(&p3);
        *reinterpret_cast<uint4*>(smem + SM_Z + row * 512 + ((ch ^ (row & 7)) * 16)) = u;
    }

    // per-token ||z||^2 (L1-warm after conversion pass)
    if (tid < 128) {
        const float4* zp = reinterpret_cast<const float4*>(zptr + (size_t)tid * Cq);
        float s = 0.f;
#pragma unroll 8
        for (int i = 0; i < 64; i++) {
            float4 v = zp[i];
            s += v.x * v.x + v.y * v.y + v.z * v.z + v.w * v.w;
        }
        s_zn[tid] = s;
    }

    prefetch_c(cbfp, 0, smem + SM_C0, tid);
    asm volatile("cp.async.commit_group;" ::: "memory");

    const int T = K / TK;
    const int g = lane >> 2, t2 = (lane & 3) << 1;
    const int alr = lane & 15, alk = (lane >> 4) << 3;
    const int br = lane & 7, bn = (lane & 16) ? 8 : 0, bk = (lane & 8) ? 8 : 0;

    // main loop; t == T is the tile-0 recollect tail
    for (int t = 0; t <= T; t++) {
        asm volatile("cp.async.wait_group 0;" ::: "memory");
        __syncthreads();
        int nxt = (t < T - 1) ? (t + 1) : ((t == T - 1) ? 0 : -1);
        if (nxt >= 0) {
            prefetch_c(cbfp, nxt * TK, smem + (((t + 1) & 1) ? SM_C1 : SM_C0), tid);
            asm volatile("cp.async.commit_group;" ::: "memory");
        }
        const int k0 = (t == T) ? 0 : t * TK;
        const uint32_t cbase = sm_u32(smem + ((t & 1) ? SM_C1 : SM_C0));

        // code norms + thresholds for this warp's slice
        float cnr[8][2];
#pragma unroll
        for (int jn = 0; jn < 4; jn++)
#pragma unroll
            for (int s2 = 0; s2 < 2; s2++) {
                int c = k0 + ncol0 + jn * 16 + s2 * 8 + t2;
                cnr[jn * 2 + s2][0] = s_cnall[c];
                cnr[jn * 2 + s2][1] = s_cnall[c + 1];
            }
        float thr00 = s_thr[mrow + g],      thr01 = s_thr[mrow + g + 8];
        float thr10 = s_thr[mrow + 16 + g], thr11 = s_thr[mrow + 24 + g];

        // ---- 128x128x256 bf16 MMA tile (warp = m32 x n64) ----
        float acc[2][8][4];
#pragma unroll
        for (int mt = 0; mt < 2; mt++)
#pragma unroll
            for (int f = 0; f < 8; f++)
#pragma unroll
                for (int q = 0; q < 4; q++) acc[mt][f][q] = 0.f;

#pragma unroll 2
        for (int kk = 0; kk < 16; kk++) {
            const int kb = kk << 4;
            uint32_t a[2][4];
#pragma unroll
            for (int mt = 0; mt < 2; mt++)
                asm volatile("ldmatrix.sync.aligned.m8n8.x4.shared.b16 {%0,%1,%2,%3}, [%4];"
                             : "=r"(a[mt][0]), "=r"(a[mt][1]), "=r"(a[mt][2]), "=r"(a[mt][3])
                             : "r"(sw_addr(zbase, mrow + mt * 16 + alr, kb + alk)));
            uint32_t bf[4][4];
#pragma unroll
            for (int jn = 0; jn < 4; jn++)
                asm volatile("ldmatrix.sync.aligned.m8n8.x4.shared.b16 {%0,%1,%2,%3}, [%4];"
                             : "=r"(bf[jn][0]), "=r"(bf[jn][1]), "=r"(bf[jn][2]), "=r"(bf[jn][3])
                             : "r"(sw_addr(cbase, ncol0 + jn * 16 + bn + br, kb + bk)));
#pragma unroll
            for (int mt = 0; mt < 2; mt++)
#pragma unroll
                for (int jn = 0; jn < 4; jn++) {
                    asm volatile("mma.sync.aligned.m16n8k16.row.col.f32.bf16.bf16.f32 "
                                 "{%0,%1,%2,%3}, {%4,%5,%6,%7}, {%8,%9}, {%0,%1,%2,%3};"
                                 : "+f"(acc[mt][jn*2][0]), "+f"(acc[mt][jn*2][1]),
                                   "+f"(acc[mt][jn*2][2]), "+f"(acc[mt][jn*2][3])
                                 : "r"(a[mt][0]), "r"(a[mt][1]), "r"(a[mt][2]), "r"(a[mt][3]),
                                   "r"(bf[jn][0]), "r"(bf[jn][1]));
                    asm volatile("mma.sync.aligned.m16n8k16.row.col.f32.bf16.bf16.f32 "
                                 "{%0,%1,%2,%3}, {%4,%5,%6,%7}, {%8,%9}, {%0,%1,%2,%3};"
                                 : "+f"(acc[mt][jn*2+1][0]), "+f"(acc[mt][jn*2+1][1]),
                                   "+f"(acc[mt][jn*2+1][2]), "+f"(acc[mt][jn*2+1][3])
                                 : "r"(a[mt][0]), "r"(a[mt][1]), "r"(a[mt][2]), "r"(a[mt][3]),
                                   "r"(bf[jn][2]), "r"(bf[jn][3]));
                }
        }

        // ---- epilogue: s = cn - 2*dot; min-track; collect candidates ----
        const bool docollect = (t > 0);
        float tm00 = 3.4e38f, tm01 = 3.4e38f, tm10 = 3.4e38f, tm11 = 3.4e38f;
#pragma unroll
        for (int mt = 0; mt < 2; mt++)
#pragma unroll
            for (int jn = 0; jn < 4; jn++)
#pragma unroll
                for (int s2 = 0; s2 < 2; s2++) {
                    const float* A = acc[mt][jn * 2 + s2];
                    const int code = k0 + ncol0 + jn * 16 + s2 * 8 + t2;
                    const float c0 = cnr[jn * 2 + s2][0], c1 = cnr[jn * 2 + s2][1];
                    float sA = fmaf(A[0], -2.f, c0);
                    float sB = fmaf(A[1], -2.f, c1);
                    float sC = fmaf(A[2], -2.f, c0);
                    float sD = fmaf(A[3], -2.f, c1);
                    float lo = fminf(sA, sB), hi = fminf(sC, sD);
                    if (mt == 0) { tm00 = fminf(tm00, lo); tm01 = fminf(tm01, hi); }
                    else         { tm10 = fminf(tm10, lo); tm11 = fminf(tm11, hi); }
                    if (docollect) {
                        const float tl = mt ? thr10 : thr00;
                        const float th = mt ? thr11 : thr01;
                        const unsigned tokl = (unsigned)(mrow + mt * 16 + g) << 11;
                        const unsigned tokh = (unsigned)(mrow + mt * 16 + g + 8) << 11;
                        if (sA < tl) { unsigned ix = atomicAdd(s_cnt, 1u); if (ix < POOL) s_pool[ix] = tokl | (unsigned)code; }
                        if (sB < tl) { unsigned ix = atomicAdd(s_cnt, 1u); if (ix < POOL) s_pool[ix] = tokl | (unsigned)(code + 1); }
                        if (sC < th) { unsigned ix = atomicAdd(s_cnt, 1u); if (ix < POOL) s_pool[ix] = tokh | (unsigned)code; }
                        if (sD < th) { unsigned ix = atomicAdd(s_cnt, 1u); if (ix < POOL) s_pool[ix] = tokh | (unsigned)(code + 1); }
                    }
                }

        // per-warp token mins -> smem -> threshold update (skip on tail)
        tm00 = fminf(tm00, __shfl_xor_sync(0xffffffffu, tm00, 1));
        tm00 = fminf(tm00, __shfl_xor_sync(0xffffffffu, tm00, 2));
        tm01 = fminf(tm01, __shfl_xor_sync(0xffffffffu, tm01, 1));
        tm01 = fminf(tm01, __shfl_xor_sync(0xffffffffu, tm01, 2));
        tm10 = fminf(tm10, __shfl_xor_sync(0xffffffffu, tm10, 1));
        tm10 = fminf(tm10, __shfl_xor_sync(0xffffffffu, tm10, 2));
        tm11 = fminf(tm11, __shfl_xor_sync(0xffffffffu, tm11, 1));
        tm11 = fminf(tm11, __shfl_xor_sync(0xffffffffu, tm11, 2));
        if (t < T) {
            if ((lane & 3) == 0) {
                const int half = wid >> 2;
                s_tmin[half * 128 + mrow + g]      = tm00;
                s_tmin[half * 128 + mrow + g + 8]  = tm01;
                s_tmin[half * 128 + mrow + g + 16] = tm10;
                s_tmin[half * 128 + mrow + g + 24] = tm11;
            }
            __syncthreads();
            if (tid < 128) {
                float m = fminf(s_tmin[tid], s_tmin[128 + tid]);
                s_thr[tid] = fminf(s_thr[tid], m + MARGIN);
            }
        }
    }
    __syncthreads();

    // ---- exact fp32 rescore of candidates (warp per entry) ----
    unsigned cnt = *s_cnt; if (cnt > POOL) cnt = POOL;
    for (unsigned i = wid; i < cnt; i += 8) {
        unsigned ent = s_pool[i];
        int token = ent >> 11, code = ent & 2047;
        const float4* zr = reinterpret_cast<const float4*>(zptr + (size_t)token * Cq);
        const float4* cr = reinterpret_cast<const float4*>(cb + (size_t)code * Cq);
        float4 a0 = zr[lane], a1 = zr[lane + 32];
        float4 b0 = cr[lane], b1 = cr[lane + 32];
        float p = a0.x * b0.x;
        p = fmaf(a0.y, b0.y, p); p = fmaf(a0.z, b0.z, p); p = fmaf(a0.w, b0.w, p);
        p = fmaf(a1.x, b1.x, p); p = fmaf(a1.y, b1.y, p);
        p = fmaf(a1.z, b1.z, p); p = fmaf(a1.w, b1.w, p);
#pragma unroll
        for (int o = 16; o; o >>= 1) p += __shfl_xor_sync(0xffffffffu, p, o);
        if (lane == 0) {
            float d = __fadd_rn(__fadd_rn(s_zn[token], s_cnall[code]), -2.0f * p);
            unsigned long long key =
                ((unsigned long long)__float_as_uint(d) << 32) | (unsigned)code;
            atomicMin(&s_key[token], key);
        }
    }
    __syncthreads();

    // ---- outputs ----
    float lossv = 0.f;
    if (tid < 128) {
        unsigned long long key = s_key[tid];
        int besti   = (int)(key & 0xFFFFFFFFull);
        float bestv = __uint_as_float((unsigned int)(key >> 32));
        lossv = bestv;
        s_bidx[tid] = besti;
        out[(size_t)Bq * Nq * Cq + (size_t)b * Nq + n0 + tid] = (float)besti;
    }
#pragma unroll
    for (int o = 16; o; o >>= 1) lossv += __shfl_xor_sync(0xffffffffu, lossv, o);
    if ((tid & 31) == 0) s_warp[tid >> 5] = lossv;
    __syncthreads();
    if (tid == 0)
        g_losspart[blockIdx.y * (Nq / TN) + blockIdx.x] =
            s_warp[0] + s_warp[1] + s_warp[2] + s_warp[3];

    // z_q rows: warp-per-token, coalesced fp32 copy
    float* zq = out + ((size_t)b * Nq + n0) * Cq;
    for (int t = wid; t < TN; t += 8) {
        const float4* srcp = reinterpret_cast<const float4*>(cb + (size_t)s_bidx[t] * Cq);
        float4* dstp = reinterpret_cast<float4*>(zq + (size_t)t * Cq);
        dstp[lane]      = srcp[lane];
        dstp[lane + 32] = srcp[lane + 32];
    }
}

// ---------------------------------------------------------------------------
// deterministic final loss reduction
// ---------------------------------------------------------------------------
__global__ void loss_kernel(float* __restrict__ out) {
    __shared__ float sw[16];
    int tid = threadIdx.x;                 // 512 threads
    float v = g_losspart[tid];
#pragma unroll
    for (int o = 16; o; o >>= 1) v += __shfl_xor_sync(0xffffffffu, v, o);
    if ((tid & 31) == 0) sw[tid >> 5] = v;
    __syncthreads();
    if (tid == 0) {
        float s = 0.f;
        for (int i = 0; i < 16; i++) s += sw[i];
        out[(size_t)Bq * Nq * Cq + (size_t)Bq * Nq] = 1.25f * s / 4294967296.0f;
    }
}

extern "C" void kernel_launch(void* const* d_in, const int* in_sizes, int n_in,
                              void* d_out, int out_size) {
    const float* z_e  = (const float*)d_in[0];
    const int*   eidx = (const int*)d_in[1];
    const float* cb0  = (const float*)d_in[2];
    const float* cb1  = (const float*)d_in[3];
    const float* cb2  = (const float*)d_in[4];
    const float* cb3  = (const float*)d_in[5];
    float* out = (float*)d_out;

    cudaFuncSetAttribute(vq_main_kernel, cudaFuncAttributeMaxDynamicSharedMemorySize, SM_TOTAL);

    cnorm_cvt_kernel<<<480, 256>>>(cb0, cb1, cb2, cb3);
    schedule_kernel<<<1, 32>>>(eidx);
    dim3 grid(Nq / TN, Bq);
    vq_main_kernel<<<grid, 256, SM_TOTAL>>>(z_e, eidx, cb0, cb1, cb2, cb3, out);
    loss_kernel<<<1, 512>>>(out);
}